// round 2
// baseline (speedup 1.0000x reference)
#include <cuda_runtime.h>
#include <math.h>

#define BB 64
#define LL 128
#define HID 768
#define CDIM 256
#define SDIM 64
#define NOUT (CDIM + SDIM)      // 320
#define FEAT 321
#define NIT 30
#define EPSV 0.05f
#define L2E 1.4426950408889634f
#define NEGBIG -1e30f

// ---------------- device scratch (static: no allocations allowed) ----------
__device__ float g_Cs[BB * LL * LL];   // Cm * (L2E/EPS), 4 MB
__device__ float g_sq[BB * LL];
__device__ float g_logw[2 * BB * LL];  // log weights * L2E; [type][b][l]
__device__ float g_fused[BB * NOUT];
__device__ float g_sink[3 * BB];       // v*BB + b

// ---------------- K0a: row squared norms ------------------------------------
__global__ void k_sq(const float* __restrict__ H) {
    int warp = (blockIdx.x * blockDim.x + threadIdx.x) >> 5;
    int lane = threadIdx.x & 31;
    if (warp >= BB * LL) return;
    const float4* p = (const float4*)(H + (size_t)warp * HID);
    float s = 0.f;
#pragma unroll
    for (int t = 0; t < HID / 128; t++) {   // 6
        float4 v = p[lane + 32 * t];
        s += v.x * v.x + v.y * v.y + v.z * v.z + v.w * v.w;
    }
#pragma unroll
    for (int o = 16; o; o >>= 1) s += __shfl_down_sync(0xffffffffu, s, o);
    if (lane == 0) g_sq[warp] = s;
}

// ---------------- K0b: masks, logw, rep, fused -------------------------------
__global__ void k_rep(const float* __restrict__ H, const int* __restrict__ tt,
                      const int* __restrict__ am, const float* __restrict__ Wc,
                      const float* __restrict__ bc, const float* __restrict__ Ws,
                      const float* __restrict__ bs, const float* __restrict__ gate) {
    int b = blockIdx.x;
    int tid = threadIdx.x;  // 256
    __shared__ float s_m0[LL], s_m1[LL];
    __shared__ __align__(16) float s_rep[2 * HID];
    __shared__ int s_cnt[2];
    if (tid < 2) s_cnt[tid] = 0;
    __syncthreads();
    if (tid < LL) {
        int a = am[b * LL + tid], t = tt[b * LL + tid];
        float f0 = (a == 1 && t == 0) ? 1.f : 0.f;
        float f1 = (a == 1 && t == 1) ? 1.f : 0.f;
        s_m0[tid] = f0; s_m1[tid] = f1;
        if (f0 > 0.f) atomicAdd(&s_cnt[0], 1);
        if (f1 > 0.f) atomicAdd(&s_cnt[1], 1);
    }
    __syncthreads();
    float n0 = fmaxf((float)s_cnt[0], 1.f);
    float n1 = fmaxf((float)s_cnt[1], 1.f);
    if (tid < LL) {
        g_logw[0 * BB * LL + b * LL + tid] = s_m0[tid] > 0.f ? (-logf(n0) * L2E) : NEGBIG;
        g_logw[1 * BB * LL + b * LL + tid] = s_m1[tid] > 0.f ? (-logf(n1) * L2E) : NEGBIG;
    }
    const float* Hb = H + (size_t)b * LL * HID;
    float i0 = 1.f / n0, i1 = 1.f / n1;
    for (int d = tid; d < HID; d += 256) {
        float a0 = 0.f, a1 = 0.f;
        for (int l = 0; l < LL; l++) {
            float h = Hb[l * HID + d];
            a0 += h * s_m0[l];
            a1 += h * s_m1[l];
        }
        s_rep[d] = Hb[d];                 // cls token
        s_rep[HID + d] = a0 * i0 - a1 * i1;
    }
    __syncthreads();
    float gv = 1.f / (1.f + expf(-gate[0]));
    int wid = tid >> 5, lane = tid & 31;
    const float4* r4 = (const float4*)s_rep;
    for (int o = wid; o < NOUT; o += 8) {
        const float* w = (o < CDIM) ? (Wc + (size_t)o * 2 * HID)
                                    : (Ws + (size_t)(o - CDIM) * 2 * HID);
        const float4* w4 = (const float4*)w;
        float acc = 0.f;
#pragma unroll
        for (int t = 0; t < (2 * HID) / 128; t++) {  // 12
            float4 wv = w4[lane + 32 * t];
            float4 rv = r4[lane + 32 * t];
            acc += wv.x * rv.x + wv.y * rv.y + wv.z * rv.z + wv.w * rv.w;
        }
#pragma unroll
        for (int off = 16; off; off >>= 1) acc += __shfl_down_sync(0xffffffffu, acc, off);
        if (lane == 0) {
            float v = acc + ((o < CDIM) ? bc[o] : bs[o - CDIM]);
            float sc = (o < CDIM) ? (1.f - gv) : gv;
            g_fused[b * NOUT + o] = v * sc;
        }
    }
}

// ---------------- K1: Gram -> scaled cost matrix -----------------------------
#define BT 64
#define BK 32
__global__ void k_gram(const float* __restrict__ H) {
    int b = blockIdx.z;
    int i0 = blockIdx.y * BT, j0 = blockIdx.x * BT;
    __shared__ __align__(16) float sA[BK * (BT + 4)];
    __shared__ __align__(16) float sB[BK * (BT + 4)];
    int tid = threadIdx.x;            // 256
    int tx = tid & 15, ty = tid >> 4; // 16x16 threads, 4x4 each
    float acc[4][4] = {};
    const float* Hb = H + (size_t)b * LL * HID;
    int lr = tid >> 3;   // 0..31 (rows lr, lr+32)
    int lc = tid & 7;    // float4 column group
    for (int k0 = 0; k0 < HID; k0 += BK) {
#pragma unroll
        for (int h = 0; h < 2; h++) {
            int row = lr + 32 * h;
            float4 v = *(const float4*)(Hb + (size_t)(i0 + row) * HID + k0 + lc * 4);
            sA[(lc * 4 + 0) * (BT + 4) + row] = v.x;
            sA[(lc * 4 + 1) * (BT + 4) + row] = v.y;
            sA[(lc * 4 + 2) * (BT + 4) + row] = v.z;
            sA[(lc * 4 + 3) * (BT + 4) + row] = v.w;
            float4 u = *(const float4*)(Hb + (size_t)(j0 + row) * HID + k0 + lc * 4);
            sB[(lc * 4 + 0) * (BT + 4) + row] = u.x;
            sB[(lc * 4 + 1) * (BT + 4) + row] = u.y;
            sB[(lc * 4 + 2) * (BT + 4) + row] = u.z;
            sB[(lc * 4 + 3) * (BT + 4) + row] = u.w;
        }
        __syncthreads();
#pragma unroll
        for (int kk = 0; kk < BK; kk++) {
            float4 av = *(const float4*)&sA[kk * (BT + 4) + ty * 4];
            float4 bv = *(const float4*)&sB[kk * (BT + 4) + tx * 4];
            float ar[4] = {av.x, av.y, av.z, av.w};
            float br[4] = {bv.x, bv.y, bv.z, bv.w};
#pragma unroll
            for (int r = 0; r < 4; r++)
#pragma unroll
                for (int c = 0; c < 4; c++) acc[r][c] += ar[r] * br[c];
        }
        __syncthreads();
    }
    const float* sqb = g_sq + b * LL;
    float* out = g_Cs + (size_t)b * LL * LL;
#pragma unroll
    for (int r = 0; r < 4; r++) {
        int i = i0 + ty * 4 + r;
        float si = sqb[i];
#pragma unroll
        for (int c = 0; c < 4; c++) {
            int j = j0 + tx * 4 + c;
            float d2 = si + sqb[j] - 2.f * acc[r][c];
            d2 = fmaxf(d2, 1e-6f);
            out[i * LL + j] = sqrtf(d2) * (L2E / EPSV);
        }
    }
}

// ---------------- K2: Sinkhorn (one CTA per (batch, variant)) ----------------
__global__ void __launch_bounds__(LL) k_sink() {
    int bx = blockIdx.x;   // 0..191
    int v = bx % 3;
    int b = bx / 3;
    int tid = threadIdx.x; // 128, one row each
    __shared__ float s_u[LL], s_la[LL], s_lb[LL];
    __shared__ float s_red[4];
    int va = (v == 2) ? 1 : 0;       // v0:(a0,b1) v1:(a0,b0) v2:(a1,b1)
    int vb = (v == 1) ? 0 : 1;
    s_la[tid] = g_logw[va * BB * LL + b * LL + tid];
    s_lb[tid] = g_logw[vb * BB * LL + b * LL + tid];
    float c[LL];
    const float4* cp = (const float4*)(g_Cs + ((size_t)b * LL + tid) * LL);
#pragma unroll
    for (int t = 0; t < LL / 4; t++) {
        float4 x = cp[t];
        c[4 * t + 0] = x.x; c[4 * t + 1] = x.y; c[4 * t + 2] = x.z; c[4 * t + 3] = x.w;
    }
    float F = 0.f, G = 0.f;
    s_u[tid] = s_lb[tid];   // G starts at 0
    __syncthreads();
    for (int it = 0; it < NIT; it++) {
        float m = -3.402823466e38f;
#pragma unroll
        for (int j = 0; j < LL; j++) m = fmaxf(m, s_u[j] - c[j]);
        float s = 0.f;
#pragma unroll
        for (int j = 0; j < LL; j++) s += exp2f(s_u[j] - c[j] - m);
        F = -(m + __log2f(s));
        __syncthreads();
        s_u[tid] = s_la[tid] + F;
        __syncthreads();
        m = -3.402823466e38f;
#pragma unroll
        for (int j = 0; j < LL; j++) m = fmaxf(m, s_u[j] - c[j]);
        s = 0.f;
#pragma unroll
        for (int j = 0; j < LL; j++) s += exp2f(s_u[j] - c[j] - m);
        G = -(m + __log2f(s));
        __syncthreads();
        s_u[tid] = s_lb[tid] + G;
        __syncthreads();
    }
    float val = (exp2f(s_la[tid]) * F + exp2f(s_lb[tid]) * G) * (EPSV / L2E);
#pragma unroll
    for (int o = 16; o; o >>= 1) val += __shfl_down_sync(0xffffffffu, val, o);
    if ((tid & 31) == 0) s_red[tid >> 5] = val;
    __syncthreads();
    if (tid == 0) g_sink[v * BB + b] = s_red[0] + s_red[1] + s_red[2] + s_red[3];
}

// ---------------- K3: feature assembly + layernorm + classifier --------------
__global__ void k_final(const float* __restrict__ lnw, const float* __restrict__ lnb,
                        const float* __restrict__ Wcls, const float* __restrict__ bcls,
                        float* __restrict__ out) {
    int b = blockIdx.x, tid = threadIdx.x;  // 128
    __shared__ float s_feat[FEAT];
    __shared__ float s_r[8];
    for (int i = tid; i < FEAT; i += 128) {
        s_feat[i] = (i < NOUT)
            ? g_fused[b * NOUT + i]
            : (g_sink[b] - 0.5f * (g_sink[BB + b] + g_sink[2 * BB + b]));
    }
    __syncthreads();
    float s = 0.f, s2 = 0.f;
    for (int i = tid; i < FEAT; i += 128) {
        float x = s_feat[i];
        s += x; s2 += x * x;
    }
#pragma unroll
    for (int o = 16; o; o >>= 1) {
        s  += __shfl_down_sync(0xffffffffu, s, o);
        s2 += __shfl_down_sync(0xffffffffu, s2, o);
    }
    if ((tid & 31) == 0) { s_r[tid >> 5] = s; s_r[4 + (tid >> 5)] = s2; }
    __syncthreads();
    float S  = s_r[0] + s_r[1] + s_r[2] + s_r[3];
    float S2 = s_r[4] + s_r[5] + s_r[6] + s_r[7];
    float mu = S / (float)FEAT;
    float var = S2 / (float)FEAT - mu * mu;
    float rstd = rsqrtf(var + 1e-5f);
    float a0 = 0.f, a1 = 0.f;
    for (int i = tid; i < FEAT; i += 128) {
        float h = (s_feat[i] - mu) * rstd * lnw[i] + lnb[i];
        a0 += h * Wcls[i];
        a1 += h * Wcls[FEAT + i];
    }
#pragma unroll
    for (int o = 16; o; o >>= 1) {
        a0 += __shfl_down_sync(0xffffffffu, a0, o);
        a1 += __shfl_down_sync(0xffffffffu, a1, o);
    }
    __syncthreads();   // protect s_r reuse
    if ((tid & 31) == 0) { s_r[tid >> 5] = a0; s_r[4 + (tid >> 5)] = a1; }
    __syncthreads();
    if (tid == 0) {
        out[b * 2 + 0] = s_r[0] + s_r[1] + s_r[2] + s_r[3] + bcls[0];
        out[b * 2 + 1] = s_r[4] + s_r[5] + s_r[6] + s_r[7] + bcls[1];
    }
}

// ---------------- launch ------------------------------------------------------
extern "C" void kernel_launch(void* const* d_in, const int* in_sizes, int n_in,
                              void* d_out, int out_size) {
    const float* H    = (const float*)d_in[0];
    const int*   tt   = (const int*)d_in[1];
    const int*   am   = (const int*)d_in[2];
    const float* Wc   = (const float*)d_in[3];
    const float* bc   = (const float*)d_in[4];
    const float* Ws   = (const float*)d_in[5];
    const float* bs   = (const float*)d_in[6];
    const float* gate = (const float*)d_in[7];
    const float* lnw  = (const float*)d_in[8];
    const float* lnb  = (const float*)d_in[9];
    const float* Wcls = (const float*)d_in[10];
    const float* bcls = (const float*)d_in[11];
    float* out = (float*)d_out;

    k_sq<<<(BB * LL) / 8, 256>>>(H);
    k_rep<<<BB, 256>>>(H, tt, am, Wc, bc, Ws, bs, gate);
    k_gram<<<dim3(2, 2, BB), 256>>>(H);
    k_sink<<<3 * BB, LL>>>();
    k_final<<<BB, 128>>>(lnw, lnb, Wcls, bcls, out);
}